// round 3
// baseline (speedup 1.0000x reference)
#include <cuda_runtime.h>
#include <math.h>

#define SEQ   512
#define BATCH 128
#define INP   256
#define HID   512
#define OUTD  256
#define NBLK  128
#define NTHR  256
#define KT    32
#define HSTR2 264   // floats per k-row in duplicated staging layout (256 used + 8 pad)

// shared memory layout (floats)
#define WA_OFF 0
#define WB_OFF (768*16)
#define WO_OFF (WB_OFF + 1024*16)
#define HS_OFF (WO_OFF + 512*2)
#define HS_BUF (KT*HSTR2)
#define BA_OFF (HS_OFF + 2*HS_BUF)
#define BB_OFF (BA_OFF + 16)
#define BO_OFF (BB_OFF + 16)
#define SMEM_FLOATS (BO_OFF + 2)
#define SMEM_BYTES  (SMEM_FLOATS*4)

// output buffer offsets (floats)
#define OFF_H0 (SEQ*BATCH*OUTD)
#define OFF_C0 (OFF_H0 + BATCH*HID)
#define OFF_H1 (OFF_C0 + BATCH*HID)
#define OFF_C1 (OFF_H1 + BATCH*HID)

// double-buffered hidden states, [h][b] layout (transposed for coalesced K-staging)
__device__ float g_h0[2][HID*BATCH];
__device__ float g_h1[2][HID*BATCH];
__device__ unsigned g_count;

__global__ void reset_kernel() {
  int i = blockIdx.x*blockDim.x + threadIdx.x;
  if (i == 0) g_count = 0u;
  for (int idx = i; idx < HID*BATCH; idx += gridDim.x*blockDim.x) {
    g_h0[0][idx] = 0.f;
    g_h1[0][idx] = 0.f;
  }
}

__device__ __forceinline__ void grid_barrier(unsigned target) {
  __syncthreads();
  if (threadIdx.x == 0) {
    __threadfence();
    atomicAdd(&g_count, 1u);
    unsigned v;
    do {
      asm volatile("ld.global.acquire.gpu.u32 %0, [%1];" : "=r"(v) : "l"(&g_count) : "memory");
    } while (v < target);
  }
  __syncthreads();
}

__device__ __forceinline__ float sigf(float x) {
  return 1.0f / (1.0f + expf(-x));
}

// ---- packed f32x2 helpers ----
__device__ __forceinline__ unsigned long long pk2(float lo, float hi) {
  unsigned long long r;
  asm("mov.b64 %0, {%1, %2};" : "=l"(r) : "f"(lo), "f"(hi));
  return r;
}
__device__ __forceinline__ void ffma2(unsigned long long& d,
                                      unsigned long long a, unsigned long long b) {
  asm("fma.rn.f32x2 %0, %1, %2, %0;" : "+l"(d) : "l"(a), "l"(b));
}
__device__ __forceinline__ void unpk2(unsigned long long v, float& lo, float& hi) {
  asm("mov.b64 {%0, %1}, %2;" : "=f"(lo), "=f"(hi) : "l"(v));
}

// ---- staging: 32k x 128b chunk, global [k][b] -> smem duplicated [k][2b+{0,1}] ----
__device__ __forceinline__ void load_h_chunk(const float* src, float4 r[4]) {
  const float4* s4 = (const float4*)src;
  #pragma unroll
  for (int j = 0; j < 4; j++)
    r[j] = __ldcg(s4 + threadIdx.x + j*NTHR);
}

__device__ __forceinline__ void store_h_chunk(float* HSb, const float4 r[4]) {
  #pragma unroll
  for (int j = 0; j < 4; j++) {
    int lin = threadIdx.x + j*NTHR;     // float4 index within 32k x 128b chunk
    int kk = lin >> 5;
    int b  = (lin & 31) * 4;
    float* d = &HSb[kk*HSTR2 + 2*b];
    *(float4*)(d)     = make_float4(r[j].x, r[j].x, r[j].y, r[j].y);
    *(float4*)(d + 4) = make_float4(r[j].z, r[j].z, r[j].w, r[j].w);
  }
}

// x is [b][k] row-major per timestep: transpose + duplicate while staging
__device__ __forceinline__ void load_x_chunk(const float* xrow, int kb, float4 r[4]) {
  #pragma unroll
  for (int j = 0; j < 4; j++) {
    int lin = threadIdx.x + j*NTHR;
    int b  = lin >> 3;
    int kq = lin & 7;
    r[j] = __ldg((const float4*)(xrow + (size_t)b*INP + kb + kq*4));
  }
}

__device__ __forceinline__ void store_x_chunk(float* HSb, const float4 r[4]) {
  #pragma unroll
  for (int j = 0; j < 4; j++) {
    int lin = threadIdx.x + j*NTHR;
    int b  = lin >> 3;
    int kq = lin & 7;
    *(float2*)&HSb[(kq*4+0)*HSTR2 + 2*b] = make_float2(r[j].x, r[j].x);
    *(float2*)&HSb[(kq*4+1)*HSTR2 + 2*b] = make_float2(r[j].y, r[j].y);
    *(float2*)&HSb[(kq*4+2)*HSTR2 + 2*b] = make_float2(r[j].z, r[j].z);
    *(float2*)&HSb[(kq*4+3)*HSTR2 + 2*b] = make_float2(r[j].w, r[j].w);
  }
}

// output projection (final step only): out[tprev,b,:] = h1 @ W_out^T + b_out (2 cols)
__device__ __forceinline__ void phase_out(int tprev, const float* h1src,
                                          const float* WO, const float* BO,
                                          float* HS, float* out, int p) {
  const int tid = threadIdx.x;
  const int ob = tid >> 1;
  const int oo = tid & 1;
  float acc = BO[oo];
  float4 r[4];
  load_h_chunk(h1src, r);
  for (int kc = 0; kc < 16; kc++) {
    float* HSb = HS + (kc & 1)*HS_BUF;
    store_h_chunk(HSb, r);
    if (kc+1 < 16) load_h_chunk(h1src + (kc+1)*KT*BATCH, r);
    __syncthreads();
    const float* wo = WO + kc*KT*2 + oo;
    #pragma unroll
    for (int kk = 0; kk < KT; kk++)
      acc = fmaf(HSb[kk*HSTR2 + 2*ob], wo[kk*2], acc);
  }
  out[(size_t)(tprev*BATCH + ob)*OUTD + 2*p + oo] = acc;
}

__global__ void __launch_bounds__(NTHR, 1)
lstm_kernel(const float* __restrict__ x,
            const float* __restrict__ Wg0, const float* __restrict__ bg0,
            const float* __restrict__ Wg1, const float* __restrict__ bg1,
            const float* __restrict__ W_out, const float* __restrict__ b_out,
            float* __restrict__ out)
{
  extern __shared__ float sm[];
  float* WA = sm + WA_OFF;   // [768][16]  layer0 weight slice; col = hh*4 + gate (f,i,c,o)
  float* WB = sm + WB_OFF;   // [1024][16] layer1 weight slice
  float* WO = sm + WO_OFF;   // [512][2]   output weight slice
  float* HS = sm + HS_OFF;   // 2 x [32][HSTR2] staged activation chunk (dup layout, dbl-buffered)
  float* BA = sm + BA_OFF;
  float* BB = sm + BB_OFF;
  float* BO = sm + BO_OFF;

  const int tid = threadIdx.x;
  const int p   = blockIdx.x;     // block owns h-indices p*4 .. p*4+3, out cols 2p, 2p+1
  const int tx  = tid & 3;        // hh within block
  const int ty  = tid >> 2;       // 0..63 -> batches 2ty, 2ty+1
  const int h   = p*4 + tx;
  const int b0  = 2*ty;
  const int ob  = tid >> 1;       // out-proj batch
  const int oo  = tid & 1;        // out-proj col offset

  // ---- stage weights once (smem layout [k][hh*4 + gate], gates stacked f,i,c,o) ----
  for (int idx = tid; idx < 768*16; idx += NTHR) {
    int k = idx >> 4, c = idx & 15;
    int j = (c & 3)*HID + p*4 + (c >> 2);
    WA[idx] = __ldg(&Wg0[(size_t)j*768 + k]);
  }
  for (int idx = tid; idx < 1024*16; idx += NTHR) {
    int k = idx >> 4, c = idx & 15;
    int j = (c & 3)*HID + p*4 + (c >> 2);
    WB[idx] = __ldg(&Wg1[(size_t)j*1024 + k]);
  }
  for (int idx = tid; idx < 1024; idx += NTHR) {
    int k = idx >> 1, c = idx & 1;
    WO[idx] = __ldg(&W_out[(size_t)(2*p + c)*HID + k]);
  }
  if (tid < 16) {
    int j = (tid & 3)*HID + p*4 + (tid >> 2);
    BA[tid] = __ldg(&bg0[j]);
    BB[tid] = __ldg(&bg1[j]);
  }
  if (tid < 2) BO[tid] = __ldg(&b_out[2*p + tid]);
  __syncthreads();

  float C0a = 0.f, C0b = 0.f, C1a = 0.f, C1b = 0.f;
  unsigned nb = 0;

  for (int t = 0; t < SEQ; t++) {
    const int rb = t & 1;       // read buffer
    const int wb = rb ^ 1;      // write buffer

    // ---- layer 0: gates = [x_t | h0(t-1)] @ Wg0^T + bg0 ; update h0, C0 ----
    {
      unsigned long long a01_0 = pk2(BA[tx*4+0], BA[tx*4+1]);   // {f,i}
      unsigned long long a23_0 = pk2(BA[tx*4+2], BA[tx*4+3]);   // {c,o}
      unsigned long long a01_1 = a01_0, a23_1 = a23_0;

      float4 r[4];
      const float* xrow = x + (size_t)t*BATCH*INP;
      load_x_chunk(xrow, 0, r);
      for (int kc = 0; kc < 24; kc++) {          // K = 768: chunks 0..7 x, 8..23 h0
        float* HSb = HS + (kc & 1)*HS_BUF;
        if (kc < 8) store_x_chunk(HSb, r); else store_h_chunk(HSb, r);
        if (kc+1 < 24) {
          if (kc+1 < 8) load_x_chunk(xrow, (kc+1)*KT, r);
          else          load_h_chunk(&g_h0[rb][((kc+1)*KT - INP)*BATCH], r);
        }
        __syncthreads();
        const float* wbase = WA + kc*KT*16 + tx*4;
        const float* abase = HSb + 4*ty;
        #pragma unroll
        for (int kk = 0; kk < KT; kk++) {
          ulonglong2 wv = *(const ulonglong2*)(wbase + kk*16);     // {wf,wi},{wc,wo}
          ulonglong2 av = *(const ulonglong2*)(abase + kk*HSTR2);  // {h0,h0},{h1,h1}
          ffma2(a01_0, wv.x, av.x);
          ffma2(a23_0, wv.y, av.x);
          ffma2(a01_1, wv.x, av.y);
          ffma2(a23_1, wv.y, av.y);
        }
      }
      float af0, ai0, ac0, ao0, af1, ai1, ac1, ao1;
      unpk2(a01_0, af0, ai0); unpk2(a23_0, ac0, ao0);
      unpk2(a01_1, af1, ai1); unpk2(a23_1, ac1, ao1);
      float f0 = sigf(af0),  f1 = sigf(af1);
      float i0 = sigf(ai0),  i1 = sigf(ai1);
      float g0 = tanhf(ac0), g1 = tanhf(ac1);
      float o0 = sigf(ao0),  o1 = sigf(ao1);
      C0a = fmaf(f0, C0a, i0*g0);
      C0b = fmaf(f1, C0b, i1*g1);
      float hn0 = o0*tanhf(C0a), hn1 = o1*tanhf(C0b);
      __stcg((float2*)&g_h0[wb][h*BATCH + b0], make_float2(hn0, hn1));
      if (t == SEQ-1) {
        out[OFF_H0 + (size_t)(b0  )*HID + h] = hn0;
        out[OFF_H0 + (size_t)(b0+1)*HID + h] = hn1;
        out[OFF_C0 + (size_t)(b0  )*HID + h] = C0a;
        out[OFF_C0 + (size_t)(b0+1)*HID + h] = C0b;
      }
    }

    grid_barrier(++nb * NBLK);   // h0(t) in buffer wb complete everywhere

    // ---- layer 1: gates = [h0(t) | h1(t-1)] @ Wg1^T + bg1 ; update h1, C1.
    //      Chunks 16..31 stage h1(t-1): fold out(t-1) = h1(t-1) @ W_out^T there. ----
    {
      unsigned long long a01_0 = pk2(BB[tx*4+0], BB[tx*4+1]);
      unsigned long long a23_0 = pk2(BB[tx*4+2], BB[tx*4+3]);
      unsigned long long a01_1 = a01_0, a23_1 = a23_0;
      float acc_out = BO[oo];

      float4 r[4];
      load_h_chunk(&g_h0[wb][0], r);
      for (int kc = 0; kc < 32; kc++) {          // K = 1024: 0..15 h0(t), 16..31 h1(t-1)
        float* HSb = HS + (kc & 1)*HS_BUF;
        store_h_chunk(HSb, r);
        if (kc+1 < 32) {
          const float* src = (kc+1 < 16) ? &g_h0[wb][(kc+1)*KT*BATCH]
                                         : &g_h1[rb][((kc+1)*KT - HID)*BATCH];
          load_h_chunk(src, r);
        }
        __syncthreads();
        const float* wbase = WB + kc*KT*16 + tx*4;
        const float* abase = HSb + 4*ty;
        #pragma unroll
        for (int kk = 0; kk < KT; kk++) {
          ulonglong2 wv = *(const ulonglong2*)(wbase + kk*16);
          ulonglong2 av = *(const ulonglong2*)(abase + kk*HSTR2);
          ffma2(a01_0, wv.x, av.x);
          ffma2(a23_0, wv.y, av.x);
          ffma2(a01_1, wv.x, av.y);
          ffma2(a23_1, wv.y, av.y);
        }
        if (kc >= 16) {                          // out(t-1) partial sums
          const float* ho = HSb + 2*ob;
          const float* wo = WO + (kc-16)*KT*2 + oo;
          #pragma unroll
          for (int kk = 0; kk < KT; kk++)
            acc_out = fmaf(ho[kk*HSTR2], wo[kk*2], acc_out);
        }
      }
      if (t > 0)
        out[(size_t)((t-1)*BATCH + ob)*OUTD + 2*p + oo] = acc_out;

      float af0, ai0, ac0, ao0, af1, ai1, ac1, ao1;
      unpk2(a01_0, af0, ai0); unpk2(a23_0, ac0, ao0);
      unpk2(a01_1, af1, ai1); unpk2(a23_1, ac1, ao1);
      float f0 = sigf(af0),  f1 = sigf(af1);
      float i0 = sigf(ai0),  i1 = sigf(ai1);
      float g0 = tanhf(ac0), g1 = tanhf(ac1);
      float o0 = sigf(ao0),  o1 = sigf(ao1);
      C1a = fmaf(f0, C1a, i0*g0);
      C1b = fmaf(f1, C1b, i1*g1);
      float hn0 = o0*tanhf(C1a), hn1 = o1*tanhf(C1b);
      __stcg((float2*)&g_h1[wb][h*BATCH + b0], make_float2(hn0, hn1));
      if (t == SEQ-1) {
        out[OFF_H1 + (size_t)(b0  )*HID + h] = hn0;
        out[OFF_H1 + (size_t)(b0+1)*HID + h] = hn1;
        out[OFF_C1 + (size_t)(b0  )*HID + h] = C1a;
        out[OFF_C1 + (size_t)(b0+1)*HID + h] = C1b;
      }
    }

    grid_barrier(++nb * NBLK);   // h1(t) in buffer wb complete everywhere
  }

  // final output row: h1(SEQ-1) is in buffer 0
  phase_out(SEQ-1, &g_h1[0][0], WO, BO, HS, out, p);
}

extern "C" void kernel_launch(void* const* d_in, const int* in_sizes, int n_in,
                              void* d_out, int out_size) {
  const float* x     = (const float*)d_in[0];
  const float* Wg0   = (const float*)d_in[1];
  const float* bg0   = (const float*)d_in[2];
  const float* Wg1   = (const float*)d_in[3];
  const float* bg1   = (const float*)d_in[4];
  const float* W_out = (const float*)d_in[5];
  const float* b_out = (const float*)d_in[6];
  float* out = (float*)d_out;

  cudaFuncSetAttribute(lstm_kernel, cudaFuncAttributeMaxDynamicSharedMemorySize, SMEM_BYTES);

  reset_kernel<<<64, 256>>>();
  lstm_kernel<<<NBLK, NTHR, SMEM_BYTES>>>(x, Wg0, bg0, Wg1, bg1, W_out, b_out, out);
}

// round 7
// speedup vs baseline: 2.3278x; 2.3278x over previous
#include <cuda_runtime.h>
#include <math.h>

#define SEQ   512
#define BATCH 128
#define INP   256
#define HID   512
#define OUTD  256
#define NBLK  128
#define NTHR  256

typedef unsigned long long u64;

// ---- shared memory layout (float offsets) ----
#define WA_OFF  0                     // [768][16]  layer0 weights, col c = hu*4+gate
#define WB_OFF  (WA_OFF + 768*16)     // [1024][16] layer1 weights
#define WO_OFF  (WB_OFF + 1024*16)    // [512][2]   out-proj weights
#define ASP_OFF (WO_OFF + 1024)       // 8 warps x 2048 floats: act staging, then gate partials [b][16]
#define PO_OFF  (ASP_OFF + 8*2048)    // [4][128][2] out partials
#define BA_OFF  (PO_OFF + 1024)
#define BB_OFF  (BA_OFF + 16)
#define BO_OFF  (BB_OFF + 16)
#define SMEM_FLOATS (BO_OFF + 2)
#define SMEM_BYTES  (SMEM_FLOATS*4)   // ~188.5 KB

// ---- output buffer offsets (floats) ----
#define OFF_H0 (SEQ*BATCH*OUTD)
#define OFF_C0 (OFF_H0 + BATCH*HID)
#define OFF_H1 (OFF_C0 + BATCH*HID)
#define OFF_C1 (OFF_H1 + BATCH*HID)

__device__ float g_h0[2][HID*BATCH];                 // [h][b]
__device__ float g_h1[2][HID*BATCH];
__device__ float g_xT[(size_t)SEQ*INP*BATCH];        // x transposed to [t][k][b]
__device__ unsigned g_count;

__global__ void reset_kernel() {
  int i = blockIdx.x*blockDim.x + threadIdx.x;
  if (i == 0) g_count = 0u;
  for (int idx = i; idx < HID*BATCH; idx += gridDim.x*blockDim.x) {
    g_h0[0][idx] = 0.f;
    g_h1[0][idx] = 0.f;
  }
}

// x[t][b][k] -> g_xT[t][k][b]
__global__ void transpose_x_kernel(const float* __restrict__ x) {
  __shared__ float tile[32][33];
  int t = blockIdx.x, kt = blockIdx.y, bt = blockIdx.z;
  int lk = threadIdx.x & 31, li = threadIdx.x >> 5;
  #pragma unroll
  for (int i = li; i < 32; i += 8)
    tile[i][lk] = x[((size_t)t*BATCH + bt*32 + i)*INP + kt*32 + lk];
  __syncthreads();
  #pragma unroll
  for (int i = li; i < 32; i += 8)
    g_xT[((size_t)t*INP + kt*32 + i)*BATCH + bt*32 + lk] = tile[lk][i];
}

__device__ __forceinline__ void grid_barrier(unsigned target) {
  __syncthreads();
  if (threadIdx.x == 0) {
    __threadfence();
    atomicAdd(&g_count, 1u);
    unsigned v;
    do {
      asm volatile("ld.global.acquire.gpu.u32 %0, [%1];" : "=r"(v) : "l"(&g_count) : "memory");
    } while (v < target);
  }
  __syncthreads();
}

__device__ __forceinline__ float sigf(float x) { return 1.0f / (1.0f + expf(-x)); }

__device__ __forceinline__ u64 dup2(float v) {
  u64 r; asm("mov.b64 %0, {%1, %1};" : "=l"(r) : "f"(v)); return r;
}
__device__ __forceinline__ void ffma2(u64& d, u64 a, u64 b) {
  asm("fma.rn.f32x2 %0, %1, %2, %0;" : "+l"(d) : "l"(a), "l"(b));
}
__device__ __forceinline__ void unpk2(u64 v, float& lo, float& hi) {
  asm("mov.b64 {%0, %1}, %2;" : "=f"(lo), "=f"(hi) : "l"(v));
}

// ---- per-warp act staging: one 8k x 128b chunk (1024 floats) ----
__device__ __forceinline__ void ldg_chunk(const float* src, float4 r[8], int lane) {
  const float4* s4 = (const float4*)src;
  #pragma unroll
  for (int j = 0; j < 8; j++) r[j] = __ldcg(s4 + j*32 + lane);
}
__device__ __forceinline__ void sts_chunk(float* buf, const float4 r[8], int lane) {
  float4* b4 = (float4*)buf;
  #pragma unroll
  for (int j = 0; j < 8; j++) b4[j*32 + lane] = r[j];
}

// ---- compute 8 k on staged chunk; thread tile 8 gate-cols x 8 batches ----
template<bool FOLD>
__device__ __forceinline__ void compute8(const float* buf, const float* Wk, const float* WOk,
                                         int gg8, int bgi8, u64 (&acc)[8][4], u64 (&acco)[2][4]) {
  #pragma unroll
  for (int kk = 0; kk < 8; kk++) {
    const float* ar = buf + kk*128 + bgi8;
    ulonglong2 A0 = *(const ulonglong2*)(ar);        // {b0,b1},{b2,b3}
    ulonglong2 A1 = *(const ulonglong2*)(ar + 4);    // {b4,b5},{b6,b7}
    u64 A[4] = {A0.x, A0.y, A1.x, A1.y};
    const float* wr = Wk + kk*16 + gg8;
    float4 w0 = *(const float4*)(wr);
    float4 w1 = *(const float4*)(wr + 4);
    float wv[8] = {w0.x, w0.y, w0.z, w0.w, w1.x, w1.y, w1.z, w1.w};
    #pragma unroll
    for (int g = 0; g < 8; g++) {
      u64 wd = dup2(wv[g]);
      #pragma unroll
      for (int bp = 0; bp < 4; bp++) ffma2(acc[g][bp], wd, A[bp]);
    }
    if (FOLD) {
      float2 wo = *(const float2*)(WOk + kk*2);
      u64 wd0 = dup2(wo.x), wd1 = dup2(wo.y);
      #pragma unroll
      for (int bp = 0; bp < 4; bp++) { ffma2(acco[0][bp], wd0, A[bp]); ffma2(acco[1][bp], wd1, A[bp]); }
    }
  }
}

__global__ void __launch_bounds__(NTHR, 1)
lstm_kernel(const float* __restrict__ Wg0, const float* __restrict__ bg0,
            const float* __restrict__ Wg1, const float* __restrict__ bg1,
            const float* __restrict__ W_out, const float* __restrict__ b_out,
            float* __restrict__ out)
{
  extern __shared__ float sm[];
  float* WAs = sm + WA_OFF;
  float* WBs = sm + WB_OFF;
  float* WOs = sm + WO_OFF;
  float* ASP = sm + ASP_OFF;
  float* POs = sm + PO_OFF;
  float* BAs = sm + BA_OFF;
  float* BBs = sm + BB_OFF;
  float* BOs = sm + BO_OFF;

  const int tid  = threadIdx.x;
  const int p    = blockIdx.x;        // owns h-units p*4..p*4+3, out cols 2p,2p+1
  const int lane = tid & 31;
  const int kg   = tid >> 5;          // warp = k-slice
  const int gg8  = (lane & 1) * 8;    // gate-col group: c in [gg8, gg8+8)
  const int bgi8 = (lane >> 1) * 8;   // batch group: b in [bgi8, bgi8+8)
  float* myAS = ASP + kg*2048;        // this warp's staging (2x1024) / partial slab

  // nonlinearity ownership: (hu2, hu2+1) x batch b
  const int b   = tid & 127;
  const int hu2 = (tid >> 7) * 2;
  // out ownership: col oc, batch ob
  const int oc = tid >> 7, ob = tid & 127;

  // ---- stage weights once; c = hu*4 + gate, row j = gate*HID + p*4 + hu ----
  for (int idx = tid; idx < 768*16; idx += NTHR) {
    int k = idx >> 4, c = idx & 15;
    int j = (c & 3)*HID + p*4 + (c >> 2);
    WAs[idx] = __ldg(&Wg0[(size_t)j*768 + k]);
  }
  for (int idx = tid; idx < 1024*16; idx += NTHR) {
    int k = idx >> 4, c = idx & 15;
    int j = (c & 3)*HID + p*4 + (c >> 2);
    WBs[idx] = __ldg(&Wg1[(size_t)j*1024 + k]);
  }
  for (int idx = tid; idx < 1024; idx += NTHR) {
    int k = idx >> 1, c = idx & 1;
    WOs[idx] = __ldg(&W_out[(size_t)(2*p + c)*HID + k]);
  }
  if (tid < 16) {
    int j = (tid & 3)*HID + p*4 + (tid >> 2);
    BAs[tid] = __ldg(&bg0[j]);
    BBs[tid] = __ldg(&bg1[j]);
  }
  if (tid < 2) BOs[tid] = __ldg(&b_out[2*p + tid]);
  __syncthreads();

  float C0[2] = {0.f, 0.f}, C1[2] = {0.f, 0.f};
  unsigned nb = 0;
  u64 acco[2][4];

  for (int t = 0; t < SEQ; t++) {
    const int rb = t & 1, wb = rb ^ 1;
    const float* h0r = &g_h0[rb][0];
    const float* h1r = &g_h1[rb][0];
    const float* xTt = g_xT + (size_t)t*INP*BATCH;

    // ================= layer 0: K=768 = x(256) | h0(512), warp slice 96 k =================
    {
      u64 acc[8][4];
      #pragma unroll
      for (int g = 0; g < 8; g++)
        #pragma unroll
        for (int bp = 0; bp < 4; bp++) acc[g][bp] = 0ull;

      const int k0 = kg*96;
      float4 r[8];
      {
        const float* s = (k0 < INP) ? (xTt + (size_t)k0*BATCH) : (h0r + (size_t)(k0-INP)*BATCH);
        ldg_chunk(s, r, lane);
      }
      #pragma unroll 1
      for (int c = 0; c < 12; c++) {
        float* buf = myAS + (c & 1)*1024;
        sts_chunk(buf, r, lane);
        if (c+1 < 12) {
          int kn = k0 + (c+1)*8;
          const float* s = (kn < INP) ? (xTt + (size_t)kn*BATCH) : (h0r + (size_t)(kn-INP)*BATCH);
          ldg_chunk(s, r, lane);
        }
        compute8<false>(buf, WAs + (k0 + c*8)*16, (const float*)0, gg8, bgi8, acc, acco);
      }
      // store gate partials into this warp's slab, layout [b][16]
      #pragma unroll
      for (int g = 0; g < 8; g++)
        #pragma unroll
        for (int bp = 0; bp < 4; bp++) {
          float lo, hi; unpk2(acc[g][bp], lo, hi);
          int bb = bgi8 + 2*bp, cc = gg8 + g;
          myAS[bb*16 + cc] = lo;
          myAS[(bb+1)*16 + cc] = hi;
        }
      __syncthreads();

      // gather + nonlinearity
      float ga[8] = {0,0,0,0,0,0,0,0};
      #pragma unroll
      for (int s = 0; s < 8; s++) {
        float4 q0 = *(const float4*)(ASP + s*2048 + b*16 + hu2*4);
        float4 q1 = *(const float4*)(ASP + s*2048 + b*16 + hu2*4 + 4);
        ga[0]+=q0.x; ga[1]+=q0.y; ga[2]+=q0.z; ga[3]+=q0.w;
        ga[4]+=q1.x; ga[5]+=q1.y; ga[6]+=q1.z; ga[7]+=q1.w;
      }
      #pragma unroll
      for (int j = 0; j < 2; j++) {
        int hu = hu2 + j;
        float ft = sigf (ga[4*j+0] + BAs[hu*4+0]);
        float it = sigf (ga[4*j+1] + BAs[hu*4+1]);
        float ct = tanhf(ga[4*j+2] + BAs[hu*4+2]);
        float ot = sigf (ga[4*j+3] + BAs[hu*4+3]);
        C0[j] = fmaf(ft, C0[j], it*ct);
        float hn = ot * tanhf(C0[j]);
        __stcg(&g_h0[wb][(p*4 + hu)*BATCH + b], hn);
        if (t == SEQ-1) {
          out[OFF_H0 + (size_t)b*HID + (p*4 + hu)] = hn;
          out[OFF_C0 + (size_t)b*HID + (p*4 + hu)] = C0[j];
        }
      }
    }

    grid_barrier(++nb * NBLK);   // h0(t) complete everywhere

    // ====== layer 1: K=1024 = h0(t)(512) | h1(t-1)(512); fold out(t-1) on h1 half ======
    {
      u64 acc[8][4];
      #pragma unroll
      for (int g = 0; g < 8; g++)
        #pragma unroll
        for (int bp = 0; bp < 4; bp++) acc[g][bp] = 0ull;
      #pragma unroll
      for (int c2 = 0; c2 < 2; c2++)
        #pragma unroll
        for (int bp = 0; bp < 4; bp++) acco[c2][bp] = 0ull;

      const float* h0w = &g_h0[wb][0];
      const int k0 = kg*128;
      const bool fold = (kg >= 4);
      float4 r[8];
      {
        const float* s = (k0 < HID) ? (h0w + (size_t)k0*BATCH) : (h1r + (size_t)(k0-HID)*BATCH);
        ldg_chunk(s, r, lane);
      }
      #pragma unroll 1
      for (int c = 0; c < 16; c++) {
        float* buf = myAS + (c & 1)*1024;
        sts_chunk(buf, r, lane);
        if (c+1 < 16) {
          int kn = k0 + (c+1)*8;
          const float* s = (kn < HID) ? (h0w + (size_t)kn*BATCH) : (h1r + (size_t)(kn-HID)*BATCH);
          ldg_chunk(s, r, lane);
        }
        if (fold)
          compute8<true >(buf, WBs + (k0 + c*8)*16, WOs + (k0 + c*8 - HID)*2, gg8, bgi8, acc, acco);
        else
          compute8<false>(buf, WBs + (k0 + c*8)*16, (const float*)0, gg8, bgi8, acc, acco);
      }
      // partials
      #pragma unroll
      for (int g = 0; g < 8; g++)
        #pragma unroll
        for (int bp = 0; bp < 4; bp++) {
          float lo, hi; unpk2(acc[g][bp], lo, hi);
          int bb = bgi8 + 2*bp, cc = gg8 + g;
          myAS[bb*16 + cc] = lo;
          myAS[(bb+1)*16 + cc] = hi;
        }
      if (fold) {
        float* POw = POs + (kg-4)*256;
        #pragma unroll
        for (int c2 = 0; c2 < 2; c2++)
          #pragma unroll
          for (int bp = 0; bp < 4; bp++) {
            float lo, hi; unpk2(acco[c2][bp], lo, hi);
            int bb = bgi8 + 2*bp;
            POw[bb*2 + c2] = lo;
            POw[(bb+1)*2 + c2] = hi;
          }
      }
      __syncthreads();

      // out(t-1) gather
      if (t > 0) {
        float ao = BOs[oc];
        #pragma unroll
        for (int s = 0; s < 4; s++) ao += POs[(s*128 + ob)*2 + oc];
        out[((size_t)(t-1)*BATCH + ob)*OUTD + 2*p + oc] = ao;
      }

      // gate gather + nonlinearity
      float ga[8] = {0,0,0,0,0,0,0,0};
      #pragma unroll
      for (int s = 0; s < 8; s++) {
        float4 q0 = *(const float4*)(ASP + s*2048 + b*16 + hu2*4);
        float4 q1 = *(const float4*)(ASP + s*2048 + b*16 + hu2*4 + 4);
        ga[0]+=q0.x; ga[1]+=q0.y; ga[2]+=q0.z; ga[3]+=q0.w;
        ga[4]+=q1.x; ga[5]+=q1.y; ga[6]+=q1.z; ga[7]+=q1.w;
      }
      #pragma unroll
      for (int j = 0; j < 2; j++) {
        int hu = hu2 + j;
        float ft = sigf (ga[4*j+0] + BBs[hu*4+0]);
        float it = sigf (ga[4*j+1] + BBs[hu*4+1]);
        float ct = tanhf(ga[4*j+2] + BBs[hu*4+2]);
        float ot = sigf (ga[4*j+3] + BBs[hu*4+3]);
        C1[j] = fmaf(ft, C1[j], it*ct);
        float hn = ot * tanhf(C1[j]);
        __stcg(&g_h1[wb][(p*4 + hu)*BATCH + b], hn);
        if (t == SEQ-1) {
          out[OFF_H1 + (size_t)b*HID + (p*4 + hu)] = hn;
          out[OFF_C1 + (size_t)b*HID + (p*4 + hu)] = C1[j];
        }
      }
    }

    grid_barrier(++nb * NBLK);   // h1(t) complete everywhere
  }

  // ---- final output row t = SEQ-1: h1 is in buffer 0 ----
  {
    const float* h1f = &g_h1[0][0];
    float ao = BOs[oc];
    #pragma unroll 8
    for (int k = 0; k < HID; k++)
      ao = fmaf(__ldcg(&h1f[(size_t)k*BATCH + ob]), WOs[k*2 + oc], ao);
    out[((size_t)(SEQ-1)*BATCH + ob)*OUTD + 2*p + oc] = ao;
  }
}

extern "C" void kernel_launch(void* const* d_in, const int* in_sizes, int n_in,
                              void* d_out, int out_size) {
  const float* x     = (const float*)d_in[0];
  const float* Wg0   = (const float*)d_in[1];
  const float* bg0   = (const float*)d_in[2];
  const float* Wg1   = (const float*)d_in[3];
  const float* bg1   = (const float*)d_in[4];
  const float* W_out = (const float*)d_in[5];
  const float* b_out = (const float*)d_in[6];
  float* out = (float*)d_out;

  cudaFuncSetAttribute(lstm_kernel, cudaFuncAttributeMaxDynamicSharedMemorySize, SMEM_BYTES);

  reset_kernel<<<64, 256>>>();
  dim3 tg(SEQ, INP/32, BATCH/32);
  transpose_x_kernel<<<tg, 256>>>(x);
  lstm_kernel<<<NBLK, NTHR, SMEM_BYTES>>>(Wg0, bg0, Wg1, bg1, W_out, b_out, out);
}